// round 16
// baseline (speedup 1.0000x reference)
#include <cuda_runtime.h>
#include <cuda_bf16.h>
#include <cuda_fp16.h>
#include <math.h>

#define MAX_NN 50000

// ---------------- scratch (static device memory; no allocs) ----------------
// g_preh[n][256 uint]: fp16 half2-packed, permuted; dst half (gi>=4) has b1 FOLDED IN.
// Per (node, gi, q): uint4#0 = {nt0..nt3}, uint4#1 = {nt4..nt7}; uint4 idx = gi*8 + q*2 + h.
__device__ __align__(16) unsigned g_preh[(size_t)MAX_NN * 256];
__device__ float g_denom[MAX_NN];
__device__ float g_agg[MAX_NN * 64];              // NATURAL layout now
__device__ __align__(16) float g_b1p[256];        // layer1 bias, permuted (no half)
__device__ float g_wa2n[128];                     // Wa2 natural
// edge weights: fp16 single frags, layout [ks][cb][q], uint2 = {h(k0,k1), h(k8,k9)}
__device__ __align__(8) uint2 g_w1fh[2 * 256 * 4];   // edge W1e
__device__ __align__(8) uint2 g_w2fh[8 * 64 * 4];    // edge We2
// node kernels keep bf16x3: uint4 = {bh(k0,k1), bh(k8,k9), bl(k0,k1), bl(k8,k9)}
__device__ __align__(16) uint4 g_w1pf[4 * 512 * 4];   // node-pre W [ks(4)][cb(512)][q]
__device__ __align__(16) uint4 g_wn1f[8 * 128 * 4];   // node Wn1   [ks(8)][cb(128)][q]
__device__ __align__(16) uint4 g_wn2f[8 * 64 * 4];    // node Wn2   [ks(8)][cb(64)][q]

__device__ __forceinline__ unsigned pk2(__nv_bfloat16 a, __nv_bfloat16 b) {
    return ((unsigned)__bfloat16_as_ushort(b) << 16) | (unsigned)__bfloat16_as_ushort(a);
}

__device__ __forceinline__ uint4 mk_frag(float f0, float f1, float f2, float f3) {
    __nv_bfloat16 h0 = __float2bfloat16_rn(f0), h1 = __float2bfloat16_rn(f1);
    __nv_bfloat16 h2 = __float2bfloat16_rn(f2), h3 = __float2bfloat16_rn(f3);
    uint4 v;
    v.x = pk2(h0, h1);
    v.y = pk2(h2, h3);
    v.z = pk2(__float2bfloat16_rn(f0 - __bfloat162float(h0)),
              __float2bfloat16_rn(f1 - __bfloat162float(h1)));
    v.w = pk2(__float2bfloat16_rn(f2 - __bfloat162float(h2)),
              __float2bfloat16_rn(f3 - __bfloat162float(h3)));
    return v;
}

__device__ __forceinline__ void mma_bf16(float* c, const unsigned* a, const unsigned* b) {
    asm volatile(
        "mma.sync.aligned.m16n8k16.row.col.f32.bf16.bf16.f32 "
        "{%0,%1,%2,%3}, {%4,%5,%6,%7}, {%8,%9}, {%0,%1,%2,%3};"
        : "+f"(c[0]), "+f"(c[1]), "+f"(c[2]), "+f"(c[3])
        : "r"(a[0]), "r"(a[1]), "r"(a[2]), "r"(a[3]), "r"(b[0]), "r"(b[1]));
}

__device__ __forceinline__ void mma_f16(float* c, const unsigned* a, unsigned b0, unsigned b1) {
    asm volatile(
        "mma.sync.aligned.m16n8k16.row.col.f32.f16.f16.f32 "
        "{%0,%1,%2,%3}, {%4,%5,%6,%7}, {%8,%9}, {%0,%1,%2,%3};"
        : "+f"(c[0]), "+f"(c[1]), "+f"(c[2]), "+f"(c[3])
        : "r"(a[0]), "r"(a[1]), "r"(a[2]), "r"(a[3]), "r"(b0), "r"(b1));
}

__device__ __forceinline__ void red_add2(float* p, float x, float y) {
    asm volatile("red.global.add.v2.f32 [%0], {%1,%2};" :: "l"(p), "f"(x), "f"(y) : "memory");
}

// make {hh, hl} bf16 pair for two fp32 values (node kernels)
__device__ __forceinline__ uint2 mk_pair(float c0, float c1) {
    __nv_bfloat16 h0 = __float2bfloat16_rn(c0), h1 = __float2bfloat16_rn(c1);
    uint2 r;
    r.x = pk2(h0, h1);
    r.y = pk2(__float2bfloat16_rn(c0 - __bfloat162float(h0)),
              __float2bfloat16_rn(c1 - __bfloat162float(h1)));
    return r;
}

__device__ __forceinline__ unsigned h2u(float a, float b) {
    __half2 h = __floats2half2_rn(a, b);
    return *(unsigned*)&h;
}
__device__ __forceinline__ float2 u2f(unsigned u) {
    return __half22float2(*(__half2*)&u);
}

// col-pair index u -> interleaved word pos: pos = (u>>3)*8 + (u&3)*2 + ((u>>2)&1)
__device__ __forceinline__ int pos_of_u(int u) {
    return (u >> 3) * 8 + (u & 3) * 2 + ((u >> 2) & 1);
}

// W1e element: rows 128..159 of (We1|Wa1), k in [0,32), col in [0,256)
__device__ __forceinline__ float w1e_at(const float* We1, const float* Wa1, int k, int c) {
    return (c < 128) ? We1[(128 + k) * 128 + c] : Wa1[(128 + k) * 128 + (c - 128)];
}
// node-pre big-W element: natural out col C in [0,512), k in [0,64)
__device__ __forceinline__ float wpre_at(const float* We1, const float* Wa1, int k, int C) {
    int half = C >> 8, c = C & 255;
    int row = half * 64 + k;
    return (c < 128) ? We1[row * 128 + c] : Wa1[row * 128 + (c - 128)];
}

// ---------------- weight packing ----------------
__global__ void pack_kernel(const float* __restrict__ We1, const float* __restrict__ Wa1,
                            const float* __restrict__ be1, const float* __restrict__ ba1,
                            const float* __restrict__ We2, const float* __restrict__ Wa2,
                            const float* __restrict__ Wn1, const float* __restrict__ Wn2) {
    int i = blockIdx.x * blockDim.x + threadIdx.x;
    if (i < 256) {        // g_b1p permuted
        int ng = i >> 6, qq = (i >> 4) & 3, nt = (i >> 1) & 7, e = i & 1;
        int c = ng * 64 + nt * 8 + qq * 2 + e;
        g_b1p[i] = (c < 128) ? be1[c] : ba1[c - 128];
    }
    if (i < 128) g_wa2n[i] = Wa2[i];
    if (i < 2048) {       // g_w1fh [ks][cb][q]
        int ks = i >> 10, cb = (i >> 2) & 255, qq = i & 3;
        int ka = ks * 16 + 2 * qq;
        g_w1fh[i] = make_uint2(
            h2u(w1e_at(We1, Wa1, ka, cb),     w1e_at(We1, Wa1, ka + 1, cb)),
            h2u(w1e_at(We1, Wa1, ka + 8, cb), w1e_at(We1, Wa1, ka + 9, cb)));
    }
    if (i < 2048) {       // g_w2fh [ks][cb][q]
        int ks = i >> 8, cb = (i >> 2) & 63, qq = i & 3;
        int ka = ks * 16 + 2 * qq;
        g_w2fh[i] = make_uint2(
            h2u(We2[ka * 64 + cb],       We2[(ka + 1) * 64 + cb]),
            h2u(We2[(ka + 8) * 64 + cb], We2[(ka + 9) * 64 + cb]));
    }
    if (i < 8192) {       // g_w1pf [ks][cb][q]
        int ks = i >> 11, cb = (i >> 2) & 511, qq = i & 3;
        int ka = ks * 16 + 2 * qq;
        g_w1pf[i] = mk_frag(wpre_at(We1, Wa1, ka, cb),     wpre_at(We1, Wa1, ka + 1, cb),
                            wpre_at(We1, Wa1, ka + 8, cb), wpre_at(We1, Wa1, ka + 9, cb));
    }
    if (i < 4096) {       // g_wn1f [ks][cb][q]
        int ks = i >> 9, cb = (i >> 2) & 127, qq = i & 3;
        int ka = ks * 16 + 2 * qq;
        g_wn1f[i] = mk_frag(Wn1[ka * 128 + cb],       Wn1[(ka + 1) * 128 + cb],
                            Wn1[(ka + 8) * 128 + cb], Wn1[(ka + 9) * 128 + cb]);
    }
    if (i < 2048) {       // g_wn2f [ks][cb][q]
        int ks = i >> 8, cb = (i >> 2) & 63, qq = i & 3;
        int ka = ks * 16 + 2 * qq;
        g_wn2f[i] = mk_frag(Wn2[ka * 64 + cb],       Wn2[(ka + 1) * 64 + cb],
                            Wn2[(ka + 8) * 64 + cb], Wn2[(ka + 9) * 64 + cb]);
    }
}

__global__ void init_kernel(int nNodes) {
    int i = blockIdx.x * blockDim.x + threadIdx.x;
    int stride = gridDim.x * blockDim.x;
    float4* a4 = (float4*)g_agg;
    for (int j = i; j < nNodes * 16; j += stride) a4[j] = make_float4(0.f, 0.f, 0.f, 0.f);
    for (int j = i; j < nNodes; j += stride) g_denom[j] = 0.f;
}

// ---------------- node precompute (bf16x3 mma): preh = fp16(nf @ Wbig [+b1 in dst half]) ----------------
__global__ __launch_bounds__(256) void node_pre_kernel(const float* __restrict__ nf, int nNodes) {
    extern __shared__ char smraw[];
    __nv_bfloat16* s_ah = (__nv_bfloat16*)smraw;   // 64*72
    __nv_bfloat16* s_al = s_ah + 64 * 72;          // 64*72
    const int tid = threadIdx.x;
    const int lane = tid & 31, w = tid >> 5;
    const int fr = lane >> 2, q = lane & 3, fc2 = q * 2;
    const int n0 = blockIdx.x * 64;

    for (int i = tid; i < 64 * 64; i += 256) {
        int r = i >> 6, c = i & 63;
        int n = n0 + r;
        float v = (n < nNodes) ? __ldg(nf + (size_t)n * 64 + c) : 0.f;
        __nv_bfloat16 h = __float2bfloat16_rn(v);
        s_ah[r * 72 + c] = h;
        s_al[r * 72 + c] = __float2bfloat16_rn(v - __bfloat162float(h));
    }
    __syncthreads();

    const int mg = w & 3, ngw = w >> 2;
    const int r0 = mg * 16 + fr, r1 = r0 + 8;

    unsigned ah[4][4], al[4][4];
#pragma unroll
    for (int ks = 0; ks < 4; ks++) {
        int kb = ks * 16;
        ah[ks][0] = *(const unsigned*)(s_ah + r0 * 72 + kb + fc2);
        ah[ks][1] = *(const unsigned*)(s_ah + r1 * 72 + kb + fc2);
        ah[ks][2] = *(const unsigned*)(s_ah + r0 * 72 + kb + fc2 + 8);
        ah[ks][3] = *(const unsigned*)(s_ah + r1 * 72 + kb + fc2 + 8);
        al[ks][0] = *(const unsigned*)(s_al + r0 * 72 + kb + fc2);
        al[ks][1] = *(const unsigned*)(s_al + r1 * 72 + kb + fc2);
        al[ks][2] = *(const unsigned*)(s_al + r0 * 72 + kb + fc2 + 8);
        al[ks][3] = *(const unsigned*)(s_al + r1 * 72 + kb + fc2 + 8);
    }

#pragma unroll
    for (int nl = 0; nl < 4; nl++) {
        int gi = nl * 2 + ngw;
        float acc[8][4];
#pragma unroll
        for (int nt = 0; nt < 8; nt++)
#pragma unroll
            for (int j = 0; j < 4; j++) acc[nt][j] = 0.f;
#pragma unroll
        for (int ks = 0; ks < 4; ks++) {
#pragma unroll
            for (int nt = 0; nt < 8; nt++) {
                int cbn = gi * 64 + nt * 8 + fr;
                uint4 wb = __ldg(g_w1pf + ((ks * 512 + cbn) << 2) + q);
                unsigned bh[2] = {wb.x, wb.y};
                unsigned bl[2] = {wb.z, wb.w};
                mma_bf16(acc[nt], ah[ks], bh);
                mma_bf16(acc[nt], ah[ks], bl);
                mma_bf16(acc[nt], al[ks], bh);
            }
        }
        // quantize to fp16 half2-packed, bias folded into dst half
        uint4* gp = (uint4*)g_preh;     // row = 64 uint4
        const float4* B4 = (const float4*)g_b1p;
        int nr0 = n0 + r0, nr1 = n0 + r1;
        float4 bv[4];
#pragma unroll
        for (int m = 0; m < 4; m++)
            bv[m] = (gi >= 4) ? __ldg(B4 + (gi - 4) * 16 + q * 4 + m)
                              : make_float4(0.f, 0.f, 0.f, 0.f);
        if (nr0 < nNodes) {
            uint4 o0, o1;
            o0.x = h2u(acc[0][0] + bv[0].x, acc[0][1] + bv[0].y);
            o0.y = h2u(acc[1][0] + bv[0].z, acc[1][1] + bv[0].w);
            o0.z = h2u(acc[2][0] + bv[1].x, acc[2][1] + bv[1].y);
            o0.w = h2u(acc[3][0] + bv[1].z, acc[3][1] + bv[1].w);
            o1.x = h2u(acc[4][0] + bv[2].x, acc[4][1] + bv[2].y);
            o1.y = h2u(acc[5][0] + bv[2].z, acc[5][1] + bv[2].w);
            o1.z = h2u(acc[6][0] + bv[3].x, acc[6][1] + bv[3].y);
            o1.w = h2u(acc[7][0] + bv[3].z, acc[7][1] + bv[3].w);
            gp[(size_t)nr0 * 64 + gi * 8 + q * 2]     = o0;
            gp[(size_t)nr0 * 64 + gi * 8 + q * 2 + 1] = o1;
        }
        if (nr1 < nNodes) {
            uint4 o0, o1;
            o0.x = h2u(acc[0][2] + bv[0].x, acc[0][3] + bv[0].y);
            o0.y = h2u(acc[1][2] + bv[0].z, acc[1][3] + bv[0].w);
            o0.z = h2u(acc[2][2] + bv[1].x, acc[2][3] + bv[1].y);
            o0.w = h2u(acc[3][2] + bv[1].z, acc[3][3] + bv[1].w);
            o1.x = h2u(acc[4][2] + bv[2].x, acc[4][3] + bv[2].y);
            o1.y = h2u(acc[5][2] + bv[2].z, acc[5][3] + bv[2].w);
            o1.z = h2u(acc[6][2] + bv[3].x, acc[6][3] + bv[3].y);
            o1.w = h2u(acc[7][2] + bv[3].z, acc[7][3] + bv[3].w);
            gp[(size_t)nr1 * 64 + gi * 8 + q * 2]     = o0;
            gp[(size_t)nr1 * 64 + gi * 8 + q * 2 + 1] = o1;
        }
    }
}

// ---------------- fused edge kernel (m32 tiles, single fp16 mma, fp16 gather) ----------------
// 64 edges/block, 512 threads, 2 CTA/SM.
// Layer1: 2 mg (m32) x 8 np (n32); np -> gi = np>>1, h = np&1 (uint4 half of g_preh group).
// Layer2: 2 mg (m32) x 8 ng2 (n8). g_agg natural layout, red.add.v2.
__global__ __launch_bounds__(512, 2) void edge_kernel(
    const float* __restrict__ ef, const int* __restrict__ src, const int* __restrict__ dst,
    const float* __restrict__ be2, const float* __restrict__ ba2,
    float* __restrict__ out_e, int nEdges) {
    extern __shared__ unsigned smw[];
    unsigned* s_ef = smw;                        // 64*20 = 1280
    unsigned* s_h  = smw + 1280;                 // 64*68 = 4352
    float* s_out   = (float*)smw;                // 64*68 floats, aliases s_ef+s_h after use
    float* s_logit = (float*)(smw + 9984);       // 64
    int*   s_src   = (int*)(s_logit + 64);       // 64
    int*   s_dst   = s_src + 64;                 // 64

    const int tid = threadIdx.x;
    const int e0 = blockIdx.x * 64;
    const int lane = tid & 31, w = tid >> 5;
    const int fr = lane >> 2, q = lane & 3, fc2 = q * 2;

    if (tid < 64) s_logit[tid] = __ldg(ba2);
    if (tid >= 64 && tid < 128) {
        int i = tid - 64, e = e0 + i;
        s_src[i] = (e < nEdges) ? __ldg(src + e) : 0;
        s_dst[i] = (e < nEdges) ? __ldg(dst + e) : 0;
    }
    {   // stage ef: one float4 per thread -> 2 fp16 words
        int r = tid >> 3, m = tid & 7;
        int e = e0 + r;
        float4 v = make_float4(0.f, 0.f, 0.f, 0.f);
        if (e < nEdges) v = __ldg((const float4*)ef + (size_t)e * 8 + m);
        s_ef[r * 20 + pos_of_u(2 * m)]     = h2u(v.x, v.y);
        s_ef[r * 20 + pos_of_u(2 * m + 1)] = h2u(v.z, v.w);
    }
    __syncthreads();

    const int mg = w & 1;
    const int rbase = mg * 32 + fr;   // rows: rbase + 8*j, j=0..3

    // ================= Layer 1 (m32 x n32) =================
    {
        const int np = w >> 1;            // 0..7
        const int gi = np >> 1, hh = np & 1;
        float acc[2][4][4];
        {   // fp16 gather-init: 1 uint4 per (row, node-half)
            const uint4* Ph = (const uint4*)g_preh;
            int off = gi * 8 + q * 2 + hh;
#pragma unroll
            for (int g = 0; g < 2; g++) {
                int rA = rbase + g * 16, rB = rA + 8;
                uint4 sA = __ldg(Ph + (size_t)s_src[rA] * 64 + off);
                uint4 dA = __ldg(Ph + (size_t)s_dst[rA] * 64 + 32 + off);
                uint4 sB = __ldg(Ph + (size_t)s_src[rB] * 64 + off);
                uint4 dB = __ldg(Ph + (size_t)s_dst[rB] * 64 + 32 + off);
                unsigned sa[4] = {sA.x, sA.y, sA.z, sA.w};
                unsigned da[4] = {dA.x, dA.y, dA.z, dA.w};
                unsigned sb[4] = {sB.x, sB.y, sB.z, sB.w};
                unsigned db[4] = {dB.x, dB.y, dB.z, dB.w};
#pragma unroll
                for (int nt = 0; nt < 4; nt++) {
                    float2 x0 = u2f(sa[nt]), y0 = u2f(da[nt]);
                    float2 x1 = u2f(sb[nt]), y1 = u2f(db[nt]);
                    acc[g][nt][0] = x0.x + y0.x;  acc[g][nt][1] = x0.y + y0.y;
                    acc[g][nt][2] = x1.x + y1.x;  acc[g][nt][3] = x1.y + y1.y;
                }
            }
        }
        // += ef @ W1e (single fp16 mma)
#pragma unroll
        for (int ks = 0; ks < 2; ks++) {
            unsigned a[2][4];
#pragma unroll
            for (int g = 0; g < 2; g++) {
                int rA = rbase + g * 16, rB = rA + 8;
                uint2 ua0 = *(const uint2*)(s_ef + rA * 20 + ks * 8 + q * 2);
                uint2 ua1 = *(const uint2*)(s_ef + rB * 20 + ks * 8 + q * 2);
                a[g][0] = ua0.x; a[g][1] = ua1.x; a[g][2] = ua0.y; a[g][3] = ua1.y;
            }
#pragma unroll
            for (int nt = 0; nt < 4; nt++) {
                int cb = gi * 64 + (hh * 4 + nt) * 8 + fr;
                uint2 wb = __ldg(g_w1fh + ((ks * 256 + cb) << 2) + q);
                mma_f16(acc[0][nt], a[0], wb.x, wb.y);
                mma_f16(acc[1][nt], a[1], wb.x, wb.y);
            }
        }
        // ReLU: We-half (np<4) -> fp16 smem; Wa-half -> logit partials (fp32)
        if (np < 4) {
#pragma unroll
            for (int g = 0; g < 2; g++) {
                int rA = rbase + g * 16, rB = rA + 8;
#pragma unroll
                for (int nt = 0; nt < 4; nt++) {
                    int ntp = hh * 4 + nt;
                    int pos = (gi * 4 + (ntp >> 1)) * 8 + q * 2 + (ntp & 1);
                    s_h[rA * 68 + pos] = h2u(fmaxf(acc[g][nt][0], 0.f), fmaxf(acc[g][nt][1], 0.f));
                    s_h[rB * 68 + pos] = h2u(fmaxf(acc[g][nt][2], 0.f), fmaxf(acc[g][nt][3], 0.f));
                }
            }
        } else {
            float p[4] = {0.f, 0.f, 0.f, 0.f};
#pragma unroll
            for (int nt = 0; nt < 4; nt++) {
                int c = (gi - 2) * 64 + (hh * 4 + nt) * 8 + fc2;
                float2 wv = __ldg((const float2*)g_wa2n + (c >> 1));
                p[0] += fmaxf(acc[0][nt][0], 0.f) * wv.x + fmaxf(acc[0][nt][1], 0.f) * wv.y;
                p[1] += fmaxf(acc[0][nt][2], 0.f) * wv.x + fmaxf(acc[0][nt][3], 0.f) * wv.y;
                p[2] += fmaxf(acc[1][nt][0], 0.f) * wv.x + fmaxf(acc[1][nt][1], 0.f) * wv.y;
                p[3] += fmaxf(acc[1][nt][2], 0.f) * wv.x + fmaxf(acc[1][nt][3], 0.f) * wv.y;
            }
#pragma unroll
            for (int j = 0; j < 4; j++) {
                p[j] += __shfl_xor_sync(0xFFFFFFFFu, p[j], 1);
                p[j] += __shfl_xor_sync(0xFFFFFFFFu, p[j], 2);
            }
            if (q == 0) {
                atomicAdd(&s_logit[rbase],      p[0]);
                atomicAdd(&s_logit[rbase + 8],  p[1]);
                atomicAdd(&s_logit[rbase + 16], p[2]);
                atomicAdd(&s_logit[rbase + 24], p[3]);
            }
        }
    }
    __syncthreads();

    // ================= Layer 2 (m32 x n8, single fp16 mma) =================
    const int ng2 = w >> 1;   // 0..7
    float acc2[2][4];
#pragma unroll
    for (int g = 0; g < 2; g++)
#pragma unroll
        for (int j = 0; j < 4; j++) acc2[g][j] = 0.f;
#pragma unroll
    for (int ks = 0; ks < 8; ks++) {
        unsigned a[2][4];
#pragma unroll
        for (int g = 0; g < 2; g++) {
            int rA = rbase + g * 16, rB = rA + 8;
            uint2 ua0 = *(const uint2*)(s_h + rA * 68 + ks * 8 + q * 2);
            uint2 ua1 = *(const uint2*)(s_h + rB * 68 + ks * 8 + q * 2);
            a[g][0] = ua0.x; a[g][1] = ua1.x; a[g][2] = ua0.y; a[g][3] = ua1.y;
        }
        int cb = ng2 * 8 + fr;
        uint2 wb = __ldg(g_w2fh + ((ks * 64 + cb) << 2) + q);
        mma_f16(acc2[0], a[0], wb.x, wb.y);
        mma_f16(acc2[1], a[1], wb.x, wb.y);
    }

    // ---- epilogue: scatter (natural g_agg, red.v2) + staged out_e ----
    {
        float2 b2 = __ldg((const float2*)be2 + ng2 * 4 + q);
        float vv[4][2];
        int rows[4];
#pragma unroll
        for (int g = 0; g < 2; g++) {
            rows[2 * g]     = rbase + g * 16;
            rows[2 * g + 1] = rbase + g * 16 + 8;
            vv[2 * g][0]     = acc2[g][0] + b2.x;  vv[2 * g][1]     = acc2[g][1] + b2.y;
            vv[2 * g + 1][0] = acc2[g][2] + b2.x;  vv[2 * g + 1][1] = acc2[g][3] + b2.y;
        }
#pragma unroll
        for (int j = 0; j < 4; j++) {
            int r = rows[j];
            if (e0 + r < nEdges) {
                float ex = expf(s_logit[r]);
                red_add2(&g_agg[s_dst[r] * 64 + ng2 * 8 + fc2], vv[j][0] * ex, vv[j][1] * ex);
            }
        }
        if (ng2 == 0 && q == 0) {
#pragma unroll
            for (int j = 0; j < 4; j++) {
                int r = rows[j];
                if (e0 + r < nEdges) atomicAdd(&g_denom[s_dst[r]], expf(s_logit[r]));
            }
        }
        __syncthreads();   // s_ef/s_h dead -> s_out aliases them
#pragma unroll
        for (int j = 0; j < 4; j++)
            *(float2*)(s_out + rows[j] * 68 + ng2 * 8 + fc2) = make_float2(vv[j][0], vv[j][1]);
    }
    __syncthreads();
    {   // coalesced write: 512 threads x 2 float4 = 64 edges x 64 floats
        int base = tid * 4;
#pragma unroll
        for (int h = 0; h < 2; h++) {
            int j = base + h * 2048;
            int e = j >> 6, c = j & 63;
            if (e0 + e < nEdges) {
                float4 v = *(const float4*)(s_out + e * 68 + c);
                *(float4*)(out_e + (size_t)(e0 + e) * 64 + c) = v;
            }
        }
    }
}

// ---------------- node MLP (bf16x3 mma, interleaved-fragment smem) ----------------
__global__ __launch_bounds__(256) void node_kernel(
    const float* __restrict__ nf,
    const float* __restrict__ bn1, const float* __restrict__ bn2,
    float* __restrict__ out_n, int nNodes) {
    extern __shared__ unsigned smw[];
    unsigned* s_x = smw;             // 64*144 words
    unsigned* s_h = smw + 64 * 144;  // 64*144 words
    const int tid = threadIdx.x;
    const int lane = tid & 31, w = tid >> 5;
    const int fr = lane >> 2, q = lane & 3, fc2 = q * 2;
    const int n0 = blockIdx.x * 64;

    for (int i = tid; i < 64 * 64; i += 256) {
        int r = i >> 6, u = i & 63;     // col pair (2u, 2u+1) of 128
        int n = n0 + r;
        float2 v = make_float2(0.f, 0.f);
        if (n < nNodes) {
            if (u < 32) {   // agg cols, NATURAL layout
                float dn = fmaxf(g_denom[n], 1e-38f);
                float2 av = *(const float2*)(g_agg + (size_t)n * 64 + 2 * u);
                v.x = av.x / dn; v.y = av.y / dn;
            } else {
                v = __ldg((const float2*)(nf + (size_t)n * 64) + (u - 32));
            }
        }
        *(uint2*)(s_x + r * 144 + pos_of_u(u) * 2) = mk_pair(v.x, v.y);
    }
    __syncthreads();

    const int mg = w & 3, ng = w >> 2;
    const int r0 = mg * 16 + fr, r1 = r0 + 8;

    // ---- layer1: h = relu(x @ Wn1 + bn1) ----
    {
        float acc[8][4];
#pragma unroll
        for (int nt = 0; nt < 8; nt++) {
            int c = ng * 64 + nt * 8 + fc2;
            float2 bv = __ldg((const float2*)bn1 + (c >> 1));
            acc[nt][0] = bv.x; acc[nt][1] = bv.y;
            acc[nt][2] = bv.x; acc[nt][3] = bv.y;
        }
#pragma unroll
        for (int ks = 0; ks < 8; ks++) {
            uint4 va0 = *(const uint4*)(s_x + r0 * 144 + ks * 16 + q * 4);
            uint4 va1 = *(const uint4*)(s_x + r1 * 144 + ks * 16 + q * 4);
            unsigned ah[4] = {va0.x, va1.x, va0.z, va1.z};
            unsigned al[4] = {va0.y, va1.y, va0.w, va1.w};
#pragma unroll
            for (int nt = 0; nt < 8; nt++) {
                int cb = ng * 64 + nt * 8 + fr;
                uint4 wb = __ldg(g_wn1f + ((ks * 128 + cb) << 2) + q);
                unsigned bh[2] = {wb.x, wb.y};
                unsigned bl[2] = {wb.z, wb.w};
                mma_bf16(acc[nt], ah, bh);
                mma_bf16(acc[nt], ah, bl);
                mma_bf16(acc[nt], al, bh);
            }
        }
#pragma unroll
        for (int nt = 0; nt < 8; nt++) {
            int pos = (ng * 4 + (nt >> 1)) * 8 + q * 2 + (nt & 1);
            *(uint2*)(s_h + r0 * 144 + pos * 2) =
                mk_pair(fmaxf(acc[nt][0], 0.f), fmaxf(acc[nt][1], 0.f));
            *(uint2*)(s_h + r1 * 144 + pos * 2) =
                mk_pair(fmaxf(acc[nt][2], 0.f), fmaxf(acc[nt][3], 0.f));
        }
    }
    __syncthreads();

    // ---- layer2: out = h @ Wn2 + bn2 ----
    const int ng2 = w >> 2;
    float acc2[4][4];
#pragma unroll
    for (int nt = 0; nt < 4; nt++) {
        int c = ng2 * 32 + nt * 8 + fc2;
        float2 bv = __ldg((const float2*)bn2 + (c >> 1));
        acc2[nt][0] = bv.x; acc2[nt][1] = bv.y;
        acc2[nt][2] = bv.x; acc2[nt][3] = bv.y;
    }
#pragma unroll
    for (int ks = 0; ks < 8; ks++) {
        uint4 va0 = *(const uint4*)(s_h + r0 * 144 + ks * 16 + q * 4);
        uint4 va1 = *(const uint4*)(s_h + r1 * 144 + ks * 16 + q * 4);
        unsigned ah[4] = {va0.x, va1.x, va0.z, va1.z};
        unsigned al[4] = {va0.y, va1.y, va0.w, va1.w};
#pragma unroll
        for (int nt = 0; nt < 4; nt++) {
            int cb = ng2 * 32 + nt * 8 + fr;
            uint4 wb = __ldg(g_wn2f + ((ks * 64 + cb) << 2) + q);
            unsigned bh[2] = {wb.x, wb.y};
            unsigned bl[2] = {wb.z, wb.w};
            mma_bf16(acc2[nt], ah, bh);
            mma_bf16(acc2[nt], ah, bl);
            mma_bf16(acc2[nt], al, bh);
        }
    }
    {
        int nr0 = n0 + r0, nr1 = n0 + r1;
#pragma unroll
        for (int nt = 0; nt < 4; nt++) {
            int c = ng2 * 32 + nt * 8 + fc2;
            if (nr0 < nNodes)
                *(float2*)(out_n + (size_t)nr0 * 64 + c) = make_float2(acc2[nt][0], acc2[nt][1]);
            if (nr1 < nNodes)
                *(float2*)(out_n + (size_t)nr1 * 64 + c) = make_float2(acc2[nt][2], acc2[nt][3]);
        }
    }
}

// ---------------- launch ----------------
extern "C" void kernel_launch(void* const* d_in, const int* in_sizes, int n_in,
                              void* d_out, int out_size) {
    const float* nf  = (const float*)d_in[0];
    const float* ef  = (const float*)d_in[1];
    const int*   src = (const int*)d_in[2];
    const int*   dst = (const int*)d_in[3];
    const float* We1 = (const float*)d_in[4];
    const float* be1 = (const float*)d_in[5];
    const float* We2 = (const float*)d_in[6];
    const float* be2 = (const float*)d_in[7];
    const float* Wa1 = (const float*)d_in[8];
    const float* ba1 = (const float*)d_in[9];
    const float* Wa2 = (const float*)d_in[10];
    const float* ba2 = (const float*)d_in[11];
    const float* Wn1 = (const float*)d_in[12];
    const float* bn1 = (const float*)d_in[13];
    const float* Wn2 = (const float*)d_in[14];
    const float* bn2 = (const float*)d_in[15];

    int nNodes = in_sizes[0] / 64;
    int nEdges = in_sizes[2];

    float* out   = (float*)d_out;
    float* out_n = out;                              // [N,64]
    float* out_e = out + (size_t)nNodes * 64;        // [E,64]

    int smem_pre  = 64 * 72 * 2 * 2;     // 18432
    int smem_edge = 10176 * 4;           // 40704
    int smem_node = (64 * 144) * 2 * 4;  // 73728

    cudaFuncSetAttribute(node_pre_kernel, cudaFuncAttributeMaxDynamicSharedMemorySize, smem_pre);
    cudaFuncSetAttribute(edge_kernel,     cudaFuncAttributeMaxDynamicSharedMemorySize, smem_edge);
    cudaFuncSetAttribute(node_kernel,     cudaFuncAttributeMaxDynamicSharedMemorySize, smem_node);

    pack_kernel<<<128, 256>>>(We1, Wa1, be1, ba1, We2, Wa2, Wn1, Wn2);
    init_kernel<<<256, 256>>>(nNodes);
    node_pre_kernel<<<(nNodes + 63) / 64, 256, smem_pre>>>(nf, nNodes);
    edge_kernel<<<(nEdges + 63) / 64, 512, smem_edge>>>(ef, src, dst, be2, ba2, out_e, nEdges);
    node_kernel<<<(nNodes + 63) / 64, 256, smem_node>>>(nf, bn1, bn2, out_n, nNodes);
}